// round 8
// baseline (speedup 1.0000x reference)
#include <cuda_runtime.h>

// Residual quantization, N=65536, D=128, M=8, K=256.
// v6: fix v5's two measured losses:
//  (1) wave quantization: grid 1024 @2CTA/SM = 3.46 waves, last wave 46% full
//      -> VB=32, grid=2048: 6.92 waves, last wave 92% full.
//  (2) LDS pressure (L1=82.4%): kk=4 tile had 4.0 FFMA2/LDS -> tx=8,kk=8,v=2
//      tile has 5.33, and with tx=8 every cc LDS.128 covers one full
//      128B-aligned bank-complete block (1 phase).
// 128 threads (tx8 x ty16), 2 vectors/thread, acc = 16 u64 (no spill at
// launch_bounds(128,2)), segment = 64 codewords, cp.async ping-pong depth 2.

#define NV 65536
#define DD 128
#define MS 8
#define KC 256
#define TPB 128
#define VB 32                     // vectors per block
#define RPAD 132                  // residual row stride (floats)
#define SROWS 64                  // codewords per segment
#define SFLOATS (SROWS * DD)      // 8192 floats = 32KB per buffer
#define NSEG (MS * KC / SROWS)    // 32 linear segments
#define SMEM_FLOATS (2 * SFLOATS + VB * RPAD + MS * KC)
#define SMEM_BYTES (SMEM_FLOATS * 4)

typedef unsigned long long u64;

__device__ float g_norms[MS * KC];

__device__ __forceinline__ void upk2(u64 v, float& lo, float& hi) {
    asm("mov.b64 {%0, %1}, %2;" : "=f"(lo), "=f"(hi) : "l"(v));
}
// Packed dual-fp32 FMA (Blackwell FFMA2), PTX-only.
__device__ __forceinline__ void ffma2(u64& d, u64 a, u64 b) {
    asm("fma.rn.f32x2 %0, %1, %2, %0;" : "+l"(d) : "l"(a), "l"(b));
}
__device__ __forceinline__ void cp16(float* dst_smem, const float* src_gmem) {
    unsigned s = (unsigned)__cvta_generic_to_shared(dst_smem);
    asm volatile("cp.async.cg.shared.global [%0], [%1], 16;" :: "r"(s), "l"(src_gmem));
}

// ---- norms: one thread per (stage, codeword) ----
__global__ void norms_kernel(const float* __restrict__ cb) {
    int m = blockIdx.x, k = threadIdx.x;
    const float4* row = (const float4*)(cb + ((size_t)m * KC + k) * DD);
    float s = 0.f;
    #pragma unroll
    for (int j = 0; j < 32; ++j) {
        float4 v = row[j];
        s = fmaf(v.x, v.x, s); s = fmaf(v.y, v.y, s);
        s = fmaf(v.z, v.z, s); s = fmaf(v.w, v.w, s);
    }
    g_norms[m * KC + k] = s;
}

// Prefetch linear segment seg (64 contiguous codebook rows) into buf, swizzled.
__device__ __forceinline__ void prefetch_seg(float* buf, const float* __restrict__ cb,
                                             int seg, int tid) {
    const float* src = cb + (size_t)seg * SFLOATS;
    #pragma unroll
    for (int t = 0; t < (SFLOATS / 4) / TPB; ++t) {     // 16 iters
        int i = tid + TPB * t;                          // 16B chunk id
        int r = i >> 5, jj = i & 31;
        cp16(buf + r * DD + 4 * (jj ^ (r & 7)), src + 4 * i);
    }
    asm volatile("cp.async.commit_group;");
}

__global__ void __launch_bounds__(TPB, 2)
rq_kernel(const float* __restrict__ x, const float* __restrict__ cb,
          float* __restrict__ out_recon, float* __restrict__ out_codes,
          float* __restrict__ out_side)
{
    extern __shared__ float sm[];
    float* sB[2] = { sm, sm + SFLOATS };   // ping-pong segment buffers (swizzled)
    float* sR = sm + 2 * SFLOATS;          // [VB][RPAD] residuals
    float* sN = sR + VB * RPAD;            // [MS*KC] norms

    const int tid = threadIdx.x;
    const int tx = tid & 7;                // codeword group (0..7)
    const int ty = tid >> 3;               // vector group (0..15)
    const int vbase = blockIdx.x * VB;

    // Kick off prefetch of segments 0 and 1 immediately.
    prefetch_seg(sB[0], cb, 0, tid);
    prefetch_seg(sB[1], cb, 1, tid);

    // ---- init: x tile -> residual smem; norms -> smem ----
    {
        const float4* xs = (const float4*)(x + (size_t)vbase * DD);
        #pragma unroll
        for (int t = 0; t < (VB * DD / 4) / TPB; ++t) {   // 8 iters
            int i = tid + TPB * t;
            int vv = i >> 5, j = i & 31;
            *(float4*)(sR + vv * RPAD + 4 * j) = xs[i];
        }
        #pragma unroll
        for (int t = 0; t < (MS * KC) / TPB; ++t)         // 16 iters
            sN[tid + TPB * t] = g_norms[tid + TPB * t];
    }

    for (int m = 0; m < MS; ++m) {
        u64 best[2];
        best[0] = ~0ull; best[1] = ~0ull;

        #pragma unroll
        for (int h = 0; h < 4; ++h) {
            const int seg = m * 4 + h;
            // Drain this segment's cp.async group (leaves only seg+1 pending).
            if (seg == NSEG - 1) asm volatile("cp.async.wait_group 0;");
            else                 asm volatile("cp.async.wait_group 1;");
            __syncthreads();   // buffer visible; also orders prev epilogue sR writes

            const float* sC = sB[seg & 1];

            // ---- distance GEMM over this segment's 64 codewords ----
            // rows tx + 8*kk; (row & 7) == tx so the swizzled j-offset is the
            // same for all kk: one joff per j, and the 8 lanes of a tx-octet
            // read 8 distinct 16B chunks of one 128B-aligned block (1 phase).
            u64 acc[16];
            #pragma unroll
            for (int i = 0; i < 16; ++i) acc[i] = 0ull;

            #pragma unroll 2
            for (int j = 0; j < 32; ++j) {
                ulonglong2 rr[2];
                #pragma unroll
                for (int v = 0; v < 2; ++v)
                    rr[v] = *(const ulonglong2*)(sR + (ty * 2 + v) * RPAD + 4 * j);
                const int joff = 16 * (j ^ tx);   // byte offset within a row
                #pragma unroll
                for (int kk = 0; kk < 8; ++kk) {
                    const char* base = (const char*)(sC + (tx + 8 * kk) * DD);
                    ulonglong2 cc = *(const ulonglong2*)(base + joff);
                    #pragma unroll
                    for (int v = 0; v < 2; ++v) {
                        ffma2(acc[kk * 2 + v], rr[v].x, cc.x);
                        ffma2(acc[kk * 2 + v], rr[v].y, cc.y);
                    }
                }
            }

            // ---- fold into per-thread argmin (sortable-bits key) ----
            #pragma unroll
            for (int kk = 0; kk < 8; ++kk) {
                int k = h * SROWS + tx + 8 * kk;
                float cn = sN[m * KC + k];
                #pragma unroll
                for (int v = 0; v < 2; ++v) {
                    float a, b;
                    upk2(acc[kk * 2 + v], a, b);
                    float d2v = fmaf(-2.0f, a + b, cn);
                    unsigned bits = __float_as_uint(d2v);
                    bits ^= (bits & 0x80000000u) ? 0xFFFFFFFFu : 0x80000000u;
                    u64 key = ((u64)bits << 32) | (unsigned)k;
                    if (key < best[v]) best[v] = key;
                }
            }

            __syncthreads();   // all warps done reading sC -> safe to overwrite
            if (seg + 2 < NSEG) prefetch_seg(sB[seg & 1], cb, seg + 2, tid);
        }

        // ---- butterfly min across the 8-lane tx octet ----
        #pragma unroll
        for (int s = 1; s < 8; s <<= 1) {
            #pragma unroll
            for (int v = 0; v < 2; ++v) {
                u64 o = __shfl_xor_sync(0xFFFFFFFFu, best[v], s);
                if (o < best[v]) best[v] = o;
            }
        }

        // ---- epilogue: winner row read from global cb (L2-hot) ----
        #pragma unroll
        for (int v = 0; v < 2; ++v) {
            const int k = (int)(unsigned)best[v];          // low 32 bits = index
            const int vec = ty * 2 + v;
            const int gvec = vbase + vec;
            const float4* crow = (const float4*)(cb + ((size_t)m * KC + k) * DD);
            #pragma unroll
            for (int t = 0; t < 4; ++t) {
                int j = tx + 8 * t;
                float4 c = __ldg(crow + j);
                float4 r = *(const float4*)(sR + vec * RPAD + 4 * j);
                r.x -= c.x; r.y -= c.y; r.z -= c.z; r.w -= c.w;
                *(float4*)(sR + vec * RPAD + 4 * j) = r;
                float4 xv = *(const float4*)(x + (size_t)gvec * DD + 4 * j);
                float4 rec = make_float4(xv.x - r.x, xv.y - r.y, xv.z - r.z, xv.w - r.w);
                *(float4*)(out_side + ((size_t)m * NV + gvec) * DD + 4 * j) = rec;
                if (m == MS - 1)
                    *(float4*)(out_recon + (size_t)gvec * DD + 4 * j) = rec;
            }
            // one-hot codes row (zero-fill folded in)
            float4* cd = (float4*)(out_codes + (size_t)gvec * (MS * KC) + (size_t)m * KC);
            const int q = k >> 2, rsel = k & 3;
            #pragma unroll
            for (int u = 0; u < 8; ++u) {
                int g = tx + 8 * u;
                float4 vv = make_float4(0.f, 0.f, 0.f, 0.f);
                if (g == q) {
                    if      (rsel == 0) vv.x = 1.f;
                    else if (rsel == 1) vv.y = 1.f;
                    else if (rsel == 2) vv.z = 1.f;
                    else                vv.w = 1.f;
                }
                cd[g] = vv;
            }
        }
    }
}

extern "C" void kernel_launch(void* const* d_in, const int* in_sizes, int n_in,
                              void* d_out, int out_size)
{
    const float* x  = (const float*)d_in[0];   // (N, D) fp32
    const float* cb = (const float*)d_in[1];   // (M, K, D) fp32

    float* out       = (float*)d_out;
    float* out_recon = out;                                // N*D
    float* out_codes = out + (size_t)NV * DD;              // N*M*K
    float* out_side  = out_codes + (size_t)NV * MS * KC;   // M*N*D

    norms_kernel<<<MS, KC>>>(cb);
    cudaFuncSetAttribute(rq_kernel, cudaFuncAttributeMaxDynamicSharedMemorySize, SMEM_BYTES);
    rq_kernel<<<NV / VB, TPB, SMEM_BYTES>>>(x, cb, out_recon, out_codes, out_side);
}